// round 9
// baseline (speedup 1.0000x reference)
#include <cuda_runtime.h>
#include <cuda_fp16.h>
#include <cstdint>

// ---------------------------------------------------------------------------
// HTSubTree, 2-kernel pipeline (fp16 operands, fp32 accumulation):
//   ht_prep : W01h[(o01*8+r02)][i01] (512x64 fp16)
//             Vth[n=(o23*8+r04)][k=(r02*64+i23)] (512x512 fp16)
//   ht_fused: per-CTA (128 out rows = 2 batches):
//       Phase A: Ah = T-chunk[128][512] fp16 in SMEM  (W01h @ X_b^T, 2 batches)
//       Phase B: out[128][512] = Ah @ Vth^T           (flat 32-chunk pipeline)
// mma.sync m16n8k16 row.col: A[m][k] row-major, B stored [n][k] n-major.
// ---------------------------------------------------------------------------

__device__ __half g_W01h[512 * 64];
__device__ __half g_Vth[512 * 512];

// ---------------- helpers --------------------------------------------------
__device__ __forceinline__ uint32_t smem_u32(const void* p) {
    uint32_t a;
    asm("{ .reg .u64 t; cvta.to.shared.u64 t, %1; cvt.u32.u64 %0, t; }" : "=r"(a) : "l"(p));
    return a;
}
__device__ __forceinline__ void cp16(uint32_t s, const void* g) {
    asm volatile("cp.async.cg.shared.global [%0], [%1], 16;" :: "r"(s), "l"(g) : "memory");
}
__device__ __forceinline__ void cp_commit() { asm volatile("cp.async.commit_group;" ::: "memory"); }
__device__ __forceinline__ void cp_wait0()  { asm volatile("cp.async.wait_group 0;" ::: "memory"); }
__device__ __forceinline__ void cp_wait1()  { asm volatile("cp.async.wait_group 1;" ::: "memory"); }

__device__ __forceinline__ void mma16(float& d0, float& d1, float& d2, float& d3,
                                      uint32_t a0, uint32_t a1, uint32_t a2, uint32_t a3,
                                      uint32_t b0, uint32_t b1) {
    asm volatile(
        "mma.sync.aligned.m16n8k16.row.col.f32.f16.f16.f32 "
        "{%0,%1,%2,%3}, {%4,%5,%6,%7}, {%8,%9}, {%0,%1,%2,%3};"
        : "+f"(d0), "+f"(d1), "+f"(d2), "+f"(d3)
        : "r"(a0), "r"(a1), "r"(a2), "r"(a3), "r"(b0), "r"(b1));
}
__device__ __forceinline__ void ldsm4(uint32_t& r0, uint32_t& r1, uint32_t& r2,
                                      uint32_t& r3, uint32_t addr) {
    asm volatile("ldmatrix.sync.aligned.m8n8.x4.shared.b16 {%0,%1,%2,%3}, [%4];"
                 : "=r"(r0), "=r"(r1), "=r"(r2), "=r"(r3) : "r"(addr));
}

// ---------------------------------------------------------------------------
// ht_prep: grid 64 (one CTA per o23), 256 threads.
// factors [p][in][out][r] (512,64,8,1); cores: c0=C04, c1=C02, c2=C24
// Computes W01h (512 entries per CTA) and Vth (4096 entries per CTA, via
// per-CTA smem W23 slice). Same arithmetic order as the R8 preps.
// ---------------------------------------------------------------------------
__global__ void ht_prep(const float* __restrict__ factors,
                        const float* __restrict__ cores) {
    __shared__ float sf[2048];
    __shared__ float sc[1536];
    __shared__ float w23s[512];      // [i23][r24] for this o23
    const int tid = threadIdx.x, blk = blockIdx.x;   // blk = o23
    for (int i = tid; i < 2048; i += 256) sf[i] = factors[i];
    for (int i = tid; i < 1536; i += 256) sc[i] = cores[i];
    __syncthreads();

    // W01h: entries [blk*512, +512)
    #pragma unroll
    for (int j = 0; j < 2; ++j) {
        int e = blk * 512 + j * 256 + tid;
        int row = e >> 6, i01 = e & 63;
        int o01 = row >> 3, r02 = row & 7;
        int o0 = o01 >> 3, o1 = o01 & 7, i0 = i01 >> 3, i1 = i01 & 7;
        const float* F0 = sf + i0 * 64 + o0 * 8;
        const float* F1 = sf + 512 + i1 * 64 + o1 * 8;
        const float* C02 = sc + 512;
        float acc = 0.f;
        #pragma unroll
        for (int r01 = 0; r01 < 8; ++r01) {
            float s = 0.f;
            #pragma unroll
            for (int r12 = 0; r12 < 8; ++r12)
                s += F1[r12] * C02[r01 * 64 + r12 * 8 + r02];
            acc += F0[r01] * s;
        }
        g_W01h[e] = __float2half_rn(acc);
    }

    // W23 slice for this o23: w23s[i23*8 + r24]
    const int o2 = blk >> 3, o3 = blk & 7;
    #pragma unroll
    for (int j = 0; j < 2; ++j) {
        int t = tid + j * 256;               // 0..511
        int i23 = t >> 3, r24 = t & 7;
        int i2 = i23 >> 3, i3 = i23 & 7;
        const float* F2 = sf + 1024 + i2 * 64 + o2 * 8;
        const float* F3 = sf + 1536 + i3 * 64 + o3 * 8;
        const float* C24 = sc + 1024;
        float acc = 0.f;
        #pragma unroll
        for (int r23 = 0; r23 < 8; ++r23) {
            float s = 0.f;
            #pragma unroll
            for (int r34 = 0; r34 < 8; ++r34)
                s += F3[r34] * C24[r23 * 64 + r34 * 8 + r24];
            acc += F2[r23] * s;
        }
        w23s[t] = acc;
    }
    __syncthreads();

    // Vth for this o23: (r02, i23, r04) — 4096 entries
    const float* C04 = sc;
    #pragma unroll
    for (int it = 0; it < 16; ++it) {
        int idx = it * 256 + tid;            // 0..4095
        int r02 = idx >> 9, rem = idx & 511;
        int i23 = rem >> 3, r04 = rem & 7;
        const float* w = w23s + i23 * 8;
        const float* c = C04 + r02 * 64 + r04;
        float acc = 0.f;
        #pragma unroll
        for (int r24 = 0; r24 < 8; ++r24) acc += w[r24] * c[r24 * 8];
        int n = blk * 8 + r04, k = r02 * 64 + i23;
        g_Vth[(size_t)n * 512 + k] = __float2half_rn(acc);
    }
}

// ---------------------------------------------------------------------------
// ht_fused: grid 256 (mBase = blk*128 = 2 batches), 256 threads = 8 warps.
// SMEM map (bytes):
//   [0, 133120)            Ah half[128][520]     (A panel, phase A -> B)
//   [133120, 225280)       D region:
//     phase A: W half[512][72] (73728) | Xh half[2][64][72] (18432)
//     phase B: 3 stages x B half[128][72] (18432 each = 55296)
// ---------------------------------------------------------------------------
#define AH_STRIDE 520
#define AH_BYTES  (128 * AH_STRIDE * 2)          // 133120
#define D_OFF     AH_BYTES
#define XH_OFF    (D_OFF + 512 * 72 * 2)         // 133120 + 73728
#define STG_BYTES (128 * 72 * 2)                 // 18432
#define FUSED_SMEM (AH_BYTES + 92160)            // 225280

__device__ __forceinline__ void fused_loadB(uint32_t sbase, int g, int tid) {
    int nb = g >> 3, c = g & 7;
    const __half* Bg = g_Vth + (size_t)(nb * 128) * 512 + c * 64;
    uint32_t ab = sbase + D_OFF + (uint32_t)(g % 3) * STG_BYTES;
    #pragma unroll
    for (int i = 0; i < 4; ++i) {
        int l = tid + i * 256;
        int row = l >> 3, s16 = (l & 7) * 8;
        cp16(ab + (uint32_t)(row * 72 + s16) * 2, Bg + (size_t)row * 512 + s16);
    }
    cp_commit();
}

__global__ __launch_bounds__(256, 1) void ht_fused(float* __restrict__ C,
                                                   const float* __restrict__ x) {
    extern __shared__ char smc[];
    uint32_t sbase = smem_u32(smc);
    const int tid = threadIdx.x, wid = tid >> 5, lane = tid & 31;
    const int gid = lane >> 2, tig = lane & 3;
    const int wm = wid & 3, wn = wid >> 2;
    const int blk = blockIdx.x;
    const int mBase = blk * 128, b0 = blk * 2;

    // ---- Phase A loads ----------------------------------------------------
    // W01h full (512x64) via cp.async, stride-72 rows
    #pragma unroll
    for (int i = 0; i < 16; ++i) {
        int l = tid + i * 256;
        int row = l >> 3, s16 = (l & 7) * 8;
        cp16(sbase + D_OFF + (uint32_t)(row * 72 + s16) * 2, g_W01h + row * 64 + s16);
    }
    cp_commit();
    // X for both batches: LDG (coalesced along i23) -> fp16 transposed Bs
    #pragma unroll
    for (int bb = 0; bb < 2; ++bb) {
        const float* xb = x + (size_t)(b0 + bb) * 4096;
        __half* Xh = (__half*)(smc + XH_OFF + bb * 9216);
        #pragma unroll
        for (int i = 0; i < 8; ++i) {
            int l = tid + i * 256;
            int i23 = l & 63, i01p = (l >> 6) * 2;
            float v0 = __ldg(xb + i01p * 64 + i23);
            float v1 = __ldg(xb + (i01p + 1) * 64 + i23);
            *(__half2*)(Xh + i23 * 72 + i01p) = __floats2half2_rn(v0, v1);
        }
    }
    cp_wait0();
    __syncthreads();

    // ---- Phase A mma: R[512 rows (o01,r02)][64 i23] per batch -------------
    const uint32_t aoffA = (uint32_t)D_OFF +
        ((uint32_t)((wm * 128 + (lane & 7) + ((lane >> 3) & 1) * 8) * 72
                    + ((lane >> 4) & 1) * 8)) * 2;
    const uint32_t boffA0 = (uint32_t)XH_OFF +
        ((uint32_t)((wn * 32 + (lane & 7) + ((lane >> 4) & 1) * 8) * 72
                    + ((lane >> 3) & 1) * 8)) * 2;

    #pragma unroll 1
    for (int bb = 0; bb < 2; ++bb) {
        float accA[8][4][4];
        #pragma unroll
        for (int mt = 0; mt < 8; ++mt)
            #pragma unroll
            for (int nt = 0; nt < 4; ++nt)
                #pragma unroll
                for (int q = 0; q < 4; ++q) accA[mt][nt][q] = 0.f;

        const uint32_t boffA = boffA0 + (uint32_t)(bb * 9216);
        #pragma unroll
        for (int s = 0; s < 4; ++s) {
            const uint32_t kb = (uint32_t)(s * 32);
            uint32_t a[8][4], bf[2][4];
            #pragma unroll
            for (int mt = 0; mt < 8; ++mt)
                ldsm4(a[mt][0], a[mt][1], a[mt][2], a[mt][3],
                      sbase + aoffA + (uint32_t)(mt * 16 * 72 * 2) + kb);
            #pragma unroll
            for (int p = 0; p < 2; ++p)
                ldsm4(bf[p][0], bf[p][1], bf[p][2], bf[p][3],
                      sbase + boffA + (uint32_t)(p * 16 * 72 * 2) + kb);
            #pragma unroll
            for (int mt = 0; mt < 8; ++mt)
                #pragma unroll
                for (int p = 0; p < 2; ++p) {
                    mma16(accA[mt][2*p][0], accA[mt][2*p][1], accA[mt][2*p][2], accA[mt][2*p][3],
                          a[mt][0], a[mt][1], a[mt][2], a[mt][3], bf[p][0], bf[p][1]);
                    mma16(accA[mt][2*p+1][0], accA[mt][2*p+1][1], accA[mt][2*p+1][2], accA[mt][2*p+1][3],
                          a[mt][0], a[mt][1], a[mt][2], a[mt][3], bf[p][2], bf[p][3]);
                }
        }

        // scatter into Ah: row = bb*64 + o01, col = r02*64 + i23
        #pragma unroll
        for (int mt = 0; mt < 8; ++mt) {
            int rowp = wm * 128 + mt * 16 + gid;          // o01*8+r02
            int ar0 = bb * 64 + (rowp >> 3);
            int ar1 = bb * 64 + ((rowp + 8) >> 3);
            int cb  = (rowp & 7) * 64;                    // same for rowp+8
            #pragma unroll
            for (int nt = 0; nt < 4; ++nt) {
                int i23 = wn * 32 + nt * 8 + 2 * tig;
                *(__half2*)(smc + ar0 * (AH_STRIDE * 2) + (cb + i23) * 2) =
                    __floats2half2_rn(accA[mt][nt][0], accA[mt][nt][1]);
                *(__half2*)(smc + ar1 * (AH_STRIDE * 2) + (cb + i23) * 2) =
                    __floats2half2_rn(accA[mt][nt][2], accA[mt][nt][3]);
            }
        }
    }
    __syncthreads();   // Ah complete; W/X region free for B staging

    // ---- Phase B: out[128][512] = Ah @ Vth^T, flat 32-chunk pipeline ------
    const uint32_t aoffB =
        ((uint32_t)((wm * 32 + (lane & 7) + ((lane >> 3) & 1) * 8) * AH_STRIDE
                    + ((lane >> 4) & 1) * 8)) * 2;
    const uint32_t boffB =
        ((uint32_t)((wn * 64 + (lane & 7) + ((lane >> 4) & 1) * 8) * 72
                    + ((lane >> 3) & 1) * 8)) * 2;

    float acc[2][8][4];
    #pragma unroll
    for (int mt = 0; mt < 2; ++mt)
        #pragma unroll
        for (int nt = 0; nt < 8; ++nt)
            #pragma unroll
            for (int q = 0; q < 4; ++q) acc[mt][nt][q] = 0.f;

    fused_loadB(sbase, 0, tid);
    fused_loadB(sbase, 1, tid);

    #pragma unroll 1
    for (int g = 0; g < 32; ++g) {
        if (g == 31) cp_wait0(); else cp_wait1();
        __syncthreads();
        if (g + 2 < 32) fused_loadB(sbase, g + 2, tid);

        const int c = g & 7;
        const uint32_t stb = sbase + D_OFF + (uint32_t)(g % 3) * STG_BYTES;
        #pragma unroll
        for (int s = 0; s < 4; ++s) {
            const uint32_t kbA = (uint32_t)((c * 64 + s * 16) * 2);
            const uint32_t kbB = (uint32_t)(s * 32);
            uint32_t a[2][4], bf[4][4];
            ldsm4(a[0][0], a[0][1], a[0][2], a[0][3], sbase + aoffB + kbA);
            ldsm4(a[1][0], a[1][1], a[1][2], a[1][3],
                  sbase + aoffB + kbA + (uint32_t)(16 * AH_STRIDE * 2));
            #pragma unroll
            for (int p = 0; p < 4; ++p)
                ldsm4(bf[p][0], bf[p][1], bf[p][2], bf[p][3],
                      stb + boffB + kbB + (uint32_t)(p * 16 * 72 * 2));
            #pragma unroll
            for (int p = 0; p < 4; ++p) {
                #pragma unroll
                for (int mt = 0; mt < 2; ++mt) {
                    mma16(acc[mt][2*p][0], acc[mt][2*p][1], acc[mt][2*p][2], acc[mt][2*p][3],
                          a[mt][0], a[mt][1], a[mt][2], a[mt][3], bf[p][0], bf[p][1]);
                    mma16(acc[mt][2*p+1][0], acc[mt][2*p+1][1], acc[mt][2*p+1][2], acc[mt][2*p+1][3],
                          a[mt][0], a[mt][1], a[mt][2], a[mt][3], bf[p][2], bf[p][3]);
                }
            }
        }

        if (c == 7) {
            const int nBase = (g >> 3) * 128;
            #pragma unroll
            for (int mt = 0; mt < 2; ++mt) {
                int r0 = mBase + wm * 32 + mt * 16 + gid;
                #pragma unroll
                for (int nt = 0; nt < 8; ++nt) {
                    int col = nBase + wn * 64 + nt * 8 + 2 * tig;
                    *(float2*)(C + (size_t)r0 * 512 + col) =
                        make_float2(acc[mt][nt][0], acc[mt][nt][1]);
                    *(float2*)(C + (size_t)(r0 + 8) * 512 + col) =
                        make_float2(acc[mt][nt][2], acc[mt][nt][3]);
                    #pragma unroll
                    for (int q = 0; q < 4; ++q) acc[mt][nt][q] = 0.f;
                }
            }
        }
    }
}

// ---------------------------------------------------------------------------
extern "C" void kernel_launch(void* const* d_in, const int* in_sizes, int n_in,
                              void* d_out, int out_size) {
    (void)in_sizes; (void)n_in; (void)out_size;
    const float* x       = (const float*)d_in[0];
    const float* factors = (const float*)d_in[1];
    const float* cores   = (const float*)d_in[2];
    float* out = (float*)d_out;

    cudaFuncSetAttribute(ht_fused, cudaFuncAttributeMaxDynamicSharedMemorySize,
                         FUSED_SMEM);

    ht_prep<<<64, 256>>>(factors, cores);
    ht_fused<<<256, 256, FUSED_SMEM>>>(out, x);
}